// round 5
// baseline (speedup 1.0000x reference)
#include <cuda_runtime.h>
#include <cuda_bf16.h>
#include <cstdint>

// x: (16, 64, 256, 256) fp32 = 16 Mi float4.  posIdx: 64 int32.
// out = posIdx[c] ? relu(x) : x
//
// MLP=8: each thread handles 8 float4 (128 B apart per step within block tile).
// Block covers 8*256 = 2048 contiguous vec4; 16384 vec4/channel % 2048 == 0,
// so each block lies in ONE channel: c = (blockIdx.x >> 3) & 63.

__global__ void __launch_bounds__(256) partial_relu_kernel(
    const float4* __restrict__ x,
    const int* __restrict__ posIdx,
    float4* __restrict__ out)
{
    const unsigned int base = blockIdx.x * 2048u + threadIdx.x;
    const bool m = posIdx[(blockIdx.x >> 3) & 63u] != 0;   // block-uniform

    float4 v[8];
#pragma unroll
    for (int i = 0; i < 8; i++)
        v[i] = __ldcs(&x[base + i * 256u]);

    if (m) {
#pragma unroll
        for (int i = 0; i < 8; i++) {
            v[i].x = fmaxf(v[i].x, 0.0f);
            v[i].y = fmaxf(v[i].y, 0.0f);
            v[i].z = fmaxf(v[i].z, 0.0f);
            v[i].w = fmaxf(v[i].w, 0.0f);
        }
    }

#pragma unroll
    for (int i = 0; i < 8; i++)
        __stcs(&out[base + i * 256u], v[i]);
}

extern "C" void kernel_launch(void* const* d_in, const int* in_sizes, int n_in,
                              void* d_out, int out_size)
{
    const float4* x = (const float4*)d_in[0];
    const int* posIdx = (const int*)d_in[1];
    float4* out = (float4*)d_out;

    // 16777216 vec4 / 2048 per block = 8192 blocks
    partial_relu_kernel<<<8192, 256>>>(x, posIdx, out);
}